// round 15
// baseline (speedup 1.0000x reference)
#include <cuda_runtime.h>
#include <cstdint>

// Problem constants
#define T_DIM 8
#define C_DIM 4
#define NMAPS (T_DIM * C_DIM)        // 32
#define H_DIM 1024
#define W_DIM 1024
#define NUM_GRID 16
#define NCELLS (NUM_GRID * NUM_GRID) // 256
#define THRESH 0.65f
#define NUM_FG 40
#define NUM_BG 1
#define MAX_PTS 42

#define BLOCKS_PER_MAP 16            // one block per grid-row (16 cells, 64 rows)
#define NSTAGES 3                    // TMA ring depth
#define RPS 4                        // rows per stage/chunk
#define STAGE_F4 (RPS * 256)         // 1024 float4
#define STAGE_BYTES (STAGE_F4 * 16)  // 16384
#define NST_TOT 8                    // TMA covers rows 0..31 (8 stages)
#define SBUF_BYTES (NSTAGES * STAGE_BYTES)   // 49152
#define DYN_SMEM (SBUF_BYTES + 64)           // + mbarriers

// Scratch (__device__ globals; no allocations allowed)
__device__ unsigned long long g_cellpack[NMAPS * NCELLS];
__device__ unsigned long long g_blockmin[NMAPS * BLOCKS_PER_MAP];
__device__ int g_ctr[NMAPS];         // self-resetting -> graph-replay safe

__device__ __forceinline__ uint32_t cvta_smem(const void* p) {
    return (uint32_t)__cvta_generic_to_shared(p);
}
__device__ __forceinline__ void mbar_init(uint32_t a, uint32_t c) {
    asm volatile("mbarrier.init.shared.b64 [%0], %1;" :: "r"(a), "r"(c) : "memory");
}
__device__ __forceinline__ void mbar_expect(uint32_t a, uint32_t bytes) {
    asm volatile("mbarrier.arrive.expect_tx.shared.b64 _, [%0], %1;"
                 :: "r"(a), "r"(bytes) : "memory");
}
__device__ __forceinline__ void mbar_wait(uint32_t a, uint32_t parity) {
    asm volatile("{\n\t"
        ".reg .pred P;\n\t"
        "LAB_%=:\n\t"
        "mbarrier.try_wait.parity.shared.b64 P, [%0], %1;\n\t"
        "@P bra DONE_%=;\n\t"
        "bra LAB_%=;\n\t"
        "DONE_%=:\n\t"
        "}" :: "r"(a), "r"(parity) : "memory");
}
__device__ __forceinline__ void bulk_g2s(uint32_t dst, const void* src,
                                         uint32_t bytes, uint32_t mbar) {
    asm volatile(
        "cp.async.bulk.shared::cluster.global.mbarrier::complete_tx::bytes "
        "[%0], [%1], %2, [%3];"
        :: "r"(dst), "l"(src), "r"(bytes), "r"(mbar) : "memory");
}
__device__ __forceinline__ void fence_proxy_async_cta() {
    asm volatile("fence.proxy.async.shared::cta;" ::: "memory");
}

// value/index update trees (strict cmps keep EARLIEST index; indices ascend)
#define TREES(v, idx, MAXV, MAXI, MINV, MINI) do {                           \
    float    m01 = fmaxf((v).x, (v).y);                                      \
    unsigned i01 = ((v).y > (v).x) ? (idx) + 1 : (idx);                      \
    float    m23 = fmaxf((v).z, (v).w);                                      \
    unsigned i23 = ((v).w > (v).z) ? (idx) + 3 : (idx) + 2;                  \
    float    mq  = fmaxf(m01, m23);                                          \
    unsigned iq  = (m23 > m01) ? i23 : i01;                                  \
    if (mq > (MAXV)) { (MAXV) = mq; (MAXI) = iq; }                           \
    float    n01 = fminf((v).x, (v).y);                                      \
    unsigned j01 = ((v).y < (v).x) ? (idx) + 1 : (idx);                      \
    float    n23 = fminf((v).z, (v).w);                                      \
    unsigned j23 = ((v).w < (v).z) ? (idx) + 3 : (idx) + 2;                  \
    float    nq  = fminf(n01, n23);                                          \
    unsigned jq  = (n23 < n01) ? j23 : j01;                                  \
    if (nq < (MINV)) { (MINV) = nq; (MINI) = jq; }                           \
} while (0)

// ---------------------------------------------------------------------------
// Fused hybrid kernel. Block = 256 threads = one grid-row of one map (64
// rows x 1024 cols = 16 cells). Rows 0..31 via TMA bulk 3-stage ring; rows
// 32..63 via direct LDG (front-batched before each mbar wait) -> both fetch
// engines run concurrently. Two accumulator pairs, exact merge at the end.
// ---------------------------------------------------------------------------
__global__ __launch_bounds__(256) void k_fused(const float* __restrict__ sims,
                                               const int* __restrict__ osz,
                                               float* __restrict__ out,
                                               int write_nums, int nums_off) {
    extern __shared__ char smem_raw[];
    float4* sbuf = reinterpret_cast<float4*>(smem_raw);
    unsigned long long* mbar64 =
        reinterpret_cast<unsigned long long*>(smem_raw + SBUF_BYTES);

    const int b    = blockIdx.x;           // 0..511
    const int m    = b >> 4;               // map id
    const int gy   = b & 15;               // grid row within map
    const int tid  = threadIdx.x;
    const int warp = tid >> 5;
    const int lane = tid & 31;
    const int rowbase = gy << 6;           // first image row of this block

    const float* __restrict__ base = sims + (size_t)m * (H_DIM * W_DIM);
    const uint32_t sb0  = cvta_smem(&sbuf[0]);
    const uint32_t mb0  = cvta_smem(&mbar64[0]);

    if (tid == 0) {
        #pragma unroll
        for (int i = 0; i < NSTAGES; ++i) mbar_init(mb0 + 8u * i, 1);
        fence_proxy_async_cta();
    }
    __syncthreads();

    // prologue: fill the TMA ring (stages 0..NSTAGES-2)
    if (tid == 0) {
        #pragma unroll
        for (int st = 0; st < NSTAGES - 1; ++st) {
            const uint32_t bar = mb0 + 8u * st;
            mbar_expect(bar, STAGE_BYTES);
            bulk_g2s(sb0 + (uint32_t)st * STAGE_BYTES,
                     base + ((unsigned)(rowbase + st * RPS) << 10),
                     STAGE_BYTES, bar);
        }
    }

    const float INF = __int_as_float(0x7f800000);
    float    maxvA = -INF, minvA = INF, maxvB = -INF, minvB = INF;
    unsigned maxiA = 0u, miniA = 0u, maxiB = 0u, miniB = 0u;
    const unsigned colbase = (unsigned)tid << 2;

    for (int s = 0; s < NST_TOT; ++s) {
        // front-batch the LDG chunk (rows 32+4s..35+4s) BEFORE the TMA wait
        float4 g[RPS];
        const unsigned growbase = (unsigned)(rowbase + 32 + s * RPS);
        #pragma unroll
        for (int j = 0; j < RPS; ++j)
            g[j] = __ldcg(reinterpret_cast<const float4*>(
                       base + ((growbase + j) << 10) + colbase));

        // consume TMA stage s (rows 4s..4s+3)
        const int bi = s % NSTAGES;
        mbar_wait(mb0 + 8u * bi, (uint32_t)((s / NSTAGES) & 1));
        const int fb = bi * STAGE_F4;
        #pragma unroll
        for (int r = 0; r < RPS; ++r) {
            const float4 v = sbuf[fb + r * 256 + tid];
            const unsigned idx = ((unsigned)(rowbase + s * RPS + r) << 10) + colbase;
            TREES(v, idx, maxvA, maxiA, minvA, miniA);
        }
        __syncthreads();          // whole block done with buffer bi

        if (tid == 0 && s + NSTAGES - 1 < NST_TOT) {
            const int st = s + NSTAGES - 1;
            const int bj = st % NSTAGES;
            const uint32_t bar = mb0 + 8u * bj;
            mbar_expect(bar, STAGE_BYTES);
            bulk_g2s(sb0 + (uint32_t)bj * STAGE_BYTES,
                     base + ((unsigned)(rowbase + st * RPS) << 10),
                     STAGE_BYTES, bar);
        }

        // reduce the LDG chunk (indices ascend within B)
        #pragma unroll
        for (int j = 0; j < RPS; ++j) {
            const unsigned idx = ((growbase + j) << 10) + colbase;
            TREES(g[j], idx, maxvB, maxiB, minvB, miniB);
        }
    }

    // exact merge: every B index > every A index (same thread), so B wins
    // only on STRICT inequality (ties keep A = earlier index).
    float    maxv = maxvA; unsigned maxi = maxiA;
    if (maxvB > maxv) { maxv = maxvB; maxi = maxiB; }
    float    minv = minvA; unsigned mini = miniA;
    if (minvB < minv) { minv = minvB; mini = miniB; }

    // ---- cell max: lexicographic reduce within each 16-lane group ----
    #pragma unroll
    for (int o = 8; o > 0; o >>= 1) {
        float    ov = __shfl_down_sync(0xffffffffu, maxv, o);
        unsigned oi = __shfl_down_sync(0xffffffffu, maxi, o);
        if (ov > maxv || (ov == maxv && oi < maxi)) { maxv = ov; maxi = oi; }
    }
    if ((lane & 15) == 0) {
        const int cid = (gy << 4) + (tid >> 4);          // cell id 0..255
        g_cellpack[m * NCELLS + cid] =
            ((unsigned long long)__float_as_uint(maxv) << 32) | (unsigned long long)maxi;
    }

    // ---- map min: full warp reduce, then block reduce ----
    #pragma unroll
    for (int o = 16; o > 0; o >>= 1) {
        float    nv = __shfl_down_sync(0xffffffffu, minv, o);
        unsigned ni = __shfl_down_sync(0xffffffffu, mini, o);
        if (nv < minv || (nv == minv && ni < mini)) { minv = nv; mini = ni; }
    }

    __shared__ unsigned long long sminkey[8];
    if (lane == 0) {
        sminkey[warp] =
            ((unsigned long long)(__float_as_uint(minv) ^ 0x80000000u) << 32) |
            (unsigned long long)mini;
    }
    __syncthreads();

    __shared__ int s_last;
    if (tid == 0) {
        unsigned long long k = sminkey[0];
        #pragma unroll
        for (int j = 1; j < 8; ++j) k = min(k, sminkey[j]);
        g_blockmin[m * BLOCKS_PER_MAP + gy] = k;
        __threadfence();                          // publish cellpack + blockmin
        const int c = atomicAdd(&g_ctr[m], 1);
        s_last = (c == BLOCKS_PER_MAP - 1);
        if (s_last) g_ctr[m] = 0;                 // self-reset for graph replays
    }
    __syncthreads();
    if (!s_last) return;

    // ======================= selection phase (last block) ==================
    float*    sval = reinterpret_cast<float*>(smem_raw);
    unsigned* sidx = reinterpret_cast<unsigned*>(smem_raw + 1024);
    __shared__ unsigned long long s_mink;

    const unsigned long long p = g_cellpack[m * NCELLS + tid];
    const float    v   = __uint_as_float((unsigned)(p >> 32));
    const unsigned idx = (unsigned)p;
    sval[tid] = v;
    sidx[tid] = idx;

    if (tid < 32) {                               // reduce the 16 block mins
        unsigned long long k = (tid < BLOCKS_PER_MAP)
            ? g_blockmin[m * BLOCKS_PER_MAP + tid] : ~0ULL;
        #pragma unroll
        for (int o = 8; o > 0; o >>= 1)
            k = min(k, __shfl_down_sync(0xffffffffu, k, o));
        if (tid == 0) s_mink = k;
    }

    float* __restrict__ orow = out + (size_t)m * (MAX_PTS * 4);
    if (tid < MAX_PTS) {
        reinterpret_cast<float4*>(orow)[tid] = make_float4(0.f, 0.f, 0.f, 0.f);
    }

    const bool valid   = (v > THRESH);
    const int  count   = __syncthreads_count(valid);   // barrier: sval/zero done
    const int  n_valid = count < NUM_FG ? count : NUM_FG;
    const bool any_fg  = (count > 0);

    const int   t  = m / C_DIM;
    const float sx = (float)osz[t * 2 + 1] / (float)W_DIM;
    const float sy = (float)osz[t * 2 + 0] / (float)H_DIM;

    // rank = #cells strictly better: (score desc, cell-id asc) == stable argsort
    const float NEGINF = -INF;
    const float effv = valid ? v : NEGINF;
    int rank = 0;
    #pragma unroll 8
    for (int j = 0; j < NCELLS; ++j) {
        const float jv = sval[j];
        const float ej = (jv > THRESH) ? jv : NEGINF;
        rank += (int)((ej > effv) || (ej == effv && j < tid));
    }

    if (any_fg) {
        if (valid && rank < NUM_FG) {
            const float px = (float)(idx & (W_DIM - 1));
            const float py = (float)(idx >> 10);
            reinterpret_cast<float4*>(orow)[rank] =
                make_float4(px * sx, py * sy, v, 1.0f);
        }
    } else if (tid == 0) {
        float    bv = sval[0];
        unsigned bi = sidx[0];
        for (int j = 1; j < NCELLS; ++j) {
            if (sval[j] > bv || (sval[j] == bv && sidx[j] < bi)) { bv = sval[j]; bi = sidx[j]; }
        }
        const float px = (float)(bi & (W_DIM - 1));
        const float py = (float)(bi >> 10);
        reinterpret_cast<float4*>(orow)[0] = make_float4(px * sx, py * sy, bv, 1.0f);
    }

    const int fg_count = any_fg ? n_valid : 1;
    if (tid == 0) {
        const unsigned long long k = s_mink;
        const float    bvv = __uint_as_float(((unsigned)(k >> 32)) ^ 0x80000000u);
        const unsigned bii = (unsigned)k;
        const float px = (float)(bii & (W_DIM - 1));
        const float py = (float)(bii >> 10);
        reinterpret_cast<float4*>(orow)[fg_count] =
            make_float4(px * sx, py * sy, bvv, 0.0f);
        if (write_nums)
            out[nums_off + m] = (float)(fg_count + NUM_BG);
    }
}

extern "C" void kernel_launch(void* const* d_in, const int* in_sizes, int n_in,
                              void* d_out, int out_size) {
    const float* sims = (const float*)d_in[0];
    // d_in[1] = category_ids (unused by the reference computation)
    const int* osz = (const int*)d_in[2];
    float* out = (float*)d_out;

    const int pts_elems = NMAPS * MAX_PTS * 4;                 // 5376
    const int write_nums = (out_size >= pts_elems + NMAPS) ? 1 : 0;

    cudaFuncSetAttribute(k_fused, cudaFuncAttributeMaxDynamicSharedMemorySize,
                         DYN_SMEM);
    k_fused<<<NMAPS * BLOCKS_PER_MAP, 256, DYN_SMEM>>>(
        sims, osz, out, write_nums, pts_elems);
}

// round 16
// speedup vs baseline: 1.0553x; 1.0553x over previous
#include <cuda_runtime.h>
#include <cstdint>

// Problem constants
#define T_DIM 8
#define C_DIM 4
#define NMAPS (T_DIM * C_DIM)        // 32
#define H_DIM 1024
#define W_DIM 1024
#define NUM_GRID 16
#define NCELLS (NUM_GRID * NUM_GRID) // 256
#define THRESH 0.65f
#define NUM_FG 40
#define NUM_BG 1
#define MAX_PTS 42
#define BLOCKS_PER_MAP 32            // 8 warps/block, 1 cell per warp

// Scratch (__device__ globals; no allocations allowed)
__device__ unsigned long long g_cellpack[NMAPS * NCELLS];
__device__ unsigned long long g_blockmin[NMAPS * BLOCKS_PER_MAP];
__device__ int g_ctr[NMAPS];         // self-resetting -> graph-replay safe

// ---------------------------------------------------------------------------
// Fused kernel: per-cell max/argmax + per-map min, then the LAST block of
// each map performs selection + output assembly.
// grid = NMAPS * 32 blocks (each block: 8 warps = 8 cells), block = 256 thr.
// Hot loop: R2's proven branchy updates, but with TWO independent
// accumulator pairs (even/odd iterations) -> 2x ILP on the serial chain.
// ---------------------------------------------------------------------------
__global__ __launch_bounds__(256) void k_fused(const float* __restrict__ sims,
                                               const int* __restrict__ osz,
                                               float* __restrict__ out,
                                               int write_nums, int nums_off) {
    const int b    = blockIdx.x;          // 0..1023
    const int m    = b >> 5;              // map id
    const int binm = b & 31;              // block within map
    const int warp = threadIdx.x >> 5;
    const int lane = threadIdx.x & 31;
    const int cid  = (binm << 3) + warp;  // 0..255
    const int cy   = cid >> 4;
    const int cx   = cid & 15;

    const float* __restrict__ base = sims + (size_t)m * (H_DIM * W_DIM);
    const int rowsel = lane >> 4;                    // 0/1: which of the 2 rows
    const int col    = (cx << 6) + ((lane & 15) << 2);
    const unsigned idx0 = (((unsigned)((cy << 6) + rowsel)) << 10) + (unsigned)col;

    const float INF = __int_as_float(0x7f800000);
    // dual accumulator pairs: pair0 = even iterations, pair1 = odd iterations
    float    maxv0 = -INF, minv0 = INF, maxv1 = -INF, minv1 = INF;
    unsigned maxi0 = 0u, mini0 = 0u, maxi1 = 0u, mini1 = 0u;

    // 32 float4 per lane; strictly-greater/less keeps EARLIEST index within
    // each interleaved subsequence (indices ascend per pair).
    #pragma unroll 8
    for (int i = 0; i < 32; i += 2) {
        const unsigned ia = idx0 + ((unsigned)i << 11);        // +2 rows/iter
        const unsigned ib = ia + (1u << 11);
        const float4 a = *reinterpret_cast<const float4*>(base + ia);
        const float4 c = *reinterpret_cast<const float4*>(base + ib);

        if (a.x > maxv0) { maxv0 = a.x; maxi0 = ia;     }
        if (a.y > maxv0) { maxv0 = a.y; maxi0 = ia + 1; }
        if (a.z > maxv0) { maxv0 = a.z; maxi0 = ia + 2; }
        if (a.w > maxv0) { maxv0 = a.w; maxi0 = ia + 3; }
        if (a.x < minv0) { minv0 = a.x; mini0 = ia;     }
        if (a.y < minv0) { minv0 = a.y; mini0 = ia + 1; }
        if (a.z < minv0) { minv0 = a.z; mini0 = ia + 2; }
        if (a.w < minv0) { minv0 = a.w; mini0 = ia + 3; }

        if (c.x > maxv1) { maxv1 = c.x; maxi1 = ib;     }
        if (c.y > maxv1) { maxv1 = c.y; maxi1 = ib + 1; }
        if (c.z > maxv1) { maxv1 = c.z; maxi1 = ib + 2; }
        if (c.w > maxv1) { maxv1 = c.w; maxi1 = ib + 3; }
        if (c.x < minv1) { minv1 = c.x; mini1 = ib;     }
        if (c.y < minv1) { minv1 = c.y; mini1 = ib + 1; }
        if (c.z < minv1) { minv1 = c.z; mini1 = ib + 2; }
        if (c.w < minv1) { minv1 = c.w; mini1 = ib + 3; }
    }

    // exact merge of the two interleaved subsequences:
    // equal values -> smaller index is the global earliest.
    float    maxv = maxv0; unsigned maxi = maxi0;
    if (maxv1 > maxv || (maxv1 == maxv && maxi1 < maxi)) { maxv = maxv1; maxi = maxi1; }
    float    minv = minv0; unsigned mini = mini0;
    if (minv1 < minv || (minv1 == minv && mini1 < mini)) { minv = minv1; mini = mini1; }

    // warp lexicographic reduce: (max val, min idx) / (min val, min idx)
    #pragma unroll
    for (int o = 16; o > 0; o >>= 1) {
        float    ov = __shfl_down_sync(0xffffffffu, maxv, o);
        unsigned oi = __shfl_down_sync(0xffffffffu, maxi, o);
        if (ov > maxv || (ov == maxv && oi < maxi)) { maxv = ov; maxi = oi; }
        float    nv = __shfl_down_sync(0xffffffffu, minv, o);
        unsigned ni = __shfl_down_sync(0xffffffffu, mini, o);
        if (nv < minv || (nv == minv && ni < mini)) { minv = nv; mini = ni; }
    }

    __shared__ unsigned long long sminkey[8];
    if (lane == 0) {
        g_cellpack[m * NCELLS + cid] =
            ((unsigned long long)__float_as_uint(maxv) << 32) | (unsigned long long)maxi;
        // orderable transform (values are non-negative floats): bits ^ 0x80000000
        sminkey[warp] =
            ((unsigned long long)(__float_as_uint(minv) ^ 0x80000000u) << 32) |
            (unsigned long long)mini;
    }
    __syncthreads();

    __shared__ int s_last;
    if (threadIdx.x == 0) {
        unsigned long long k = sminkey[0];
        #pragma unroll
        for (int j = 1; j < 8; ++j) k = min(k, sminkey[j]);
        g_blockmin[m * BLOCKS_PER_MAP + binm] = k;
        __threadfence();                          // publish cellpack + blockmin
        const int c = atomicAdd(&g_ctr[m], 1);
        s_last = (c == BLOCKS_PER_MAP - 1);
        if (s_last) g_ctr[m] = 0;                 // self-reset for graph replays
    }
    __syncthreads();
    if (!s_last) return;

    // ======================= selection phase (last block) ==================
    const int tid = threadIdx.x;                  // == cell id

    __shared__ float    sval[NCELLS];
    __shared__ unsigned sidx[NCELLS];
    __shared__ unsigned long long s_mink;

    const unsigned long long p = g_cellpack[m * NCELLS + tid];
    const float    v   = __uint_as_float((unsigned)(p >> 32));
    const unsigned idx = (unsigned)p;
    sval[tid] = v;
    sidx[tid] = idx;

    if (tid < 32) {                               // reduce the 32 block mins
        unsigned long long k = g_blockmin[m * BLOCKS_PER_MAP + tid];
        #pragma unroll
        for (int o = 16; o > 0; o >>= 1)
            k = min(k, __shfl_down_sync(0xffffffffu, k, o));
        if (tid == 0) s_mink = k;
    }

    float* __restrict__ orow = out + (size_t)m * (MAX_PTS * 4);
    if (tid < MAX_PTS) {
        reinterpret_cast<float4*>(orow)[tid] = make_float4(0.f, 0.f, 0.f, 0.f);
    }

    const bool valid   = (v > THRESH);
    const int  count   = __syncthreads_count(valid);   // barrier: sval/zero done
    const int  n_valid = count < NUM_FG ? count : NUM_FG;
    const bool any_fg  = (count > 0);

    const int   t  = m / C_DIM;
    const float sx = (float)osz[t * 2 + 1] / (float)W_DIM;
    const float sy = (float)osz[t * 2 + 0] / (float)H_DIM;

    // rank = #cells strictly better: (score desc, cell-id asc) == stable argsort
    const float NEGINF = -INF;
    const float effv = valid ? v : NEGINF;
    int rank = 0;
    #pragma unroll 8
    for (int j = 0; j < NCELLS; ++j) {
        const float jv = sval[j];
        const float ej = (jv > THRESH) ? jv : NEGINF;
        rank += (int)((ej > effv) || (ej == effv && j < tid));
    }

    if (any_fg) {
        if (valid && rank < NUM_FG) {
            const float px = (float)(idx & (W_DIM - 1));
            const float py = (float)(idx >> 10);
            reinterpret_cast<float4*>(orow)[rank] =
                make_float4(px * sx, py * sy, v, 1.0f);
        }
    } else if (tid == 0) {
        // fallback: global argmax (value desc, idx asc) over cell maxima
        float    bv = sval[0];
        unsigned bi = sidx[0];
        for (int j = 1; j < NCELLS; ++j) {
            if (sval[j] > bv || (sval[j] == bv && sidx[j] < bi)) { bv = sval[j]; bi = sidx[j]; }
        }
        const float px = (float)(bi & (W_DIM - 1));
        const float py = (float)(bi >> 10);
        reinterpret_cast<float4*>(orow)[0] = make_float4(px * sx, py * sy, bv, 1.0f);
    }

    const int fg_count = any_fg ? n_valid : 1;
    if (tid == 0) {
        const unsigned long long k = s_mink;
        const float    bvv = __uint_as_float(((unsigned)(k >> 32)) ^ 0x80000000u);
        const unsigned bii = (unsigned)k;
        const float px = (float)(bii & (W_DIM - 1));
        const float py = (float)(bii >> 10);
        reinterpret_cast<float4*>(orow)[fg_count] =
            make_float4(px * sx, py * sy, bvv, 0.0f);
        if (write_nums)
            out[nums_off + m] = (float)(fg_count + NUM_BG);
    }
}

extern "C" void kernel_launch(void* const* d_in, const int* in_sizes, int n_in,
                              void* d_out, int out_size) {
    const float* sims = (const float*)d_in[0];
    // d_in[1] = category_ids (unused by the reference computation)
    const int* osz = (const int*)d_in[2];
    float* out = (float*)d_out;

    const int pts_elems = NMAPS * MAX_PTS * 4;                 // 5376
    const int write_nums = (out_size >= pts_elems + NMAPS) ? 1 : 0;

    k_fused<<<NMAPS * BLOCKS_PER_MAP, 256>>>(sims, osz, out, write_nums, pts_elems);
}